// round 14
// baseline (speedup 1.0000x reference)
#include <cuda_runtime.h>
#include <cuda_fp16.h>
#include <math.h>
#include <stdint.h>

#define N_HEAD 16
#define N_EMBD 1024
#define HD     64
#define B_     4
#define T_     2048
#define M_TOK  (B_ * T_)
#define C3     (3 * N_EMBD)

// Scratch (device globals — no allocation allowed in kernel_launch)
__device__ __half g_qkv_h[(size_t)M_TOK * C3];        // [B*T, 3C] fp16
__device__ __half g_att_h[(size_t)M_TOK * N_EMBD];    // attention out, fp16
__device__ __half g_x_h[(size_t)M_TOK * N_EMBD];      // x in fp16
__device__ __half g_qkvw_h[(size_t)C3 * N_EMBD];      // qkv_w fp16
__device__ __half g_projw_h[(size_t)N_EMBD * N_EMBD]; // proj_w fp16

__device__ __forceinline__ float ex2(float x) {
    float r;
    asm("ex2.approx.ftz.f32 %0, %1;" : "=f"(r) : "f"(x));
    return r;
}
__device__ __forceinline__ uint32_t smem_u32(const void* p) {
    return (uint32_t)__cvta_generic_to_shared(p);
}

// ---------------------------------------------------------------------------
// fp32 -> fp16 convert (vectorized)
// ---------------------------------------------------------------------------
__global__ __launch_bounds__(256) void f2h_kernel(
    const float* __restrict__ in, __half* __restrict__ out, int n4)
{
    int i = blockIdx.x * 256 + threadIdx.x;
    if (i < n4) {
        float4 v = *(const float4*)(in + (size_t)i * 4);
        __half2 lo = __floats2half2_rn(v.x, v.y);
        __half2 hi = __floats2half2_rn(v.z, v.w);
        uint2 o = make_uint2(*(uint32_t*)&lo, *(uint32_t*)&hi);
        *(uint2*)(out + (size_t)i * 4) = o;
    }
}

// ---------------------------------------------------------------------------
// fp16 tensor-core GEMM v4: C[M,N] = A[M,K] @ W[N,K]^T + bias[N]
// 128x128 block tile, BK=64 (128B rows), 3-stage cp.async ring in dynamic
// smem (3 x 32KB = 96KB). Swizzle: 16B chunk c -> c ^ (row & 7) gives full
// 32-bank coverage for ldmatrix. 8 warps (4M x 2N), warp tile 32x64,
// 64 MMAs per warp per 64-K iteration; ONE __syncthreads per iteration.
// ---------------------------------------------------------------------------
#define TC_DYN_BYTES (3 * 32768)

template <typename OT>
__global__ __launch_bounds__(256) void gemm_f16(
    const __half* __restrict__ A, const __half* __restrict__ W,
    const float* __restrict__ bias, OT* __restrict__ C,
    int M, int N, int K)
{
    extern __shared__ __half sm[];   // stage st: A at st*16384, B at +8192 halves

    const int tid   = threadIdx.x;
    const int warp  = tid >> 5;
    const int lane  = tid & 31;
    const int warpM = warp & 3;
    const int warpN = warp >> 2;
    const int g     = lane >> 2;
    const int t     = lane & 3;

    const __half* Ab = A + (size_t)blockIdx.y * 128 * K;
    const __half* Wb = W + (size_t)blockIdx.x * 128 * K;

    const int lr  = tid >> 1;        // load row 0..127
    const int lc0 = (tid & 1) * 4;   // first of 4 consecutive 16B chunks
    const int r7  = lr & 7;

    const int KT = K >> 6;           // 64-half K tiles

    auto issue = [&](int kt, int st) {
        __half* SA = sm + st * 16384;
        __half* SB = SA + 8192;
        const __half* ga = Ab + (size_t)lr * K + (kt << 6);
        const __half* gw = Wb + (size_t)lr * K + (kt << 6);
        #pragma unroll
        for (int i = 0; i < 4; i++) {
            int c  = lc0 + i;
            int sc = c ^ r7;
            asm volatile("cp.async.cg.shared.global [%0], [%1], 16;"
                         :: "r"(smem_u32(SA + lr * 64 + sc * 8)), "l"(ga + c * 8));
            asm volatile("cp.async.cg.shared.global [%0], [%1], 16;"
                         :: "r"(smem_u32(SB + lr * 64 + sc * 8)), "l"(gw + c * 8));
        }
        asm volatile("cp.async.commit_group;");
    };

    issue(0, 0);
    if (KT > 1) issue(1, 1);

    float acc[2][8][4];
    #pragma unroll
    for (int i = 0; i < 2; i++)
        #pragma unroll
        for (int j = 0; j < 8; j++)
            #pragma unroll
            for (int c = 0; c < 4; c++) acc[i][j][c] = 0.f;

    for (int kt = 0; kt < KT; kt++) {
        const int s = kt % 3;
        if (kt + 1 < KT) asm volatile("cp.async.wait_group 1;" ::: "memory");
        else             asm volatile("cp.async.wait_group 0;" ::: "memory");
        __syncthreads();   // all warps done reading stage (kt-1)%3 before reuse

        if (kt + 2 < KT) issue(kt + 2, (kt + 2) % 3);

        __half* SA = sm + s * 16384;
        __half* SB = SA + 8192;

        #pragma unroll
        for (int ks = 0; ks < 4; ks++) {       // 4 x k16 per 64-K tile
            uint32_t af[2][4];
            #pragma unroll
            for (int tm = 0; tm < 2; tm++) {
                int row = warpM * 32 + tm * 16 + (lane & 15);
                int c   = ks * 2 + (lane >> 4);
                int sc  = c ^ (row & 7);
                uint32_t addr = smem_u32(SA + row * 64 + sc * 8);
                asm volatile("ldmatrix.sync.aligned.m8n8.x4.shared.b16 "
                             "{%0,%1,%2,%3}, [%4];"
                             : "=r"(af[tm][0]), "=r"(af[tm][1]),
                               "=r"(af[tm][2]), "=r"(af[tm][3])
                             : "r"(addr));
            }
            uint32_t bf[8][2];
            #pragma unroll
            for (int tnp = 0; tnp < 4; tnp++) {
                int n  = warpN * 64 + tnp * 16 + ((lane >> 4) << 3) + (lane & 7);
                int c  = ks * 2 + ((lane >> 3) & 1);
                int sc = c ^ (n & 7);
                uint32_t addr = smem_u32(SB + n * 64 + sc * 8);
                asm volatile("ldmatrix.sync.aligned.m8n8.x4.shared.b16 "
                             "{%0,%1,%2,%3}, [%4];"
                             : "=r"(bf[2 * tnp][0]),     "=r"(bf[2 * tnp][1]),
                               "=r"(bf[2 * tnp + 1][0]), "=r"(bf[2 * tnp + 1][1])
                             : "r"(addr));
            }
            #pragma unroll
            for (int tn = 0; tn < 8; tn++)
                #pragma unroll
                for (int tm = 0; tm < 2; tm++) {
                    asm volatile(
                        "mma.sync.aligned.m16n8k16.row.col.f32.f16.f16.f32 "
                        "{%0,%1,%2,%3}, {%4,%5,%6,%7}, {%8,%9}, {%0,%1,%2,%3};"
                        : "+f"(acc[tm][tn][0]), "+f"(acc[tm][tn][1]),
                          "+f"(acc[tm][tn][2]), "+f"(acc[tm][tn][3])
                        : "r"(af[tm][0]), "r"(af[tm][1]),
                          "r"(af[tm][2]), "r"(af[tm][3]),
                          "r"(bf[tn][0]), "r"(bf[tn][1]));
                }
        }
    }

    #pragma unroll
    for (int tm = 0; tm < 2; tm++) {
        int row = blockIdx.y * 128 + warpM * 32 + tm * 16 + g;
        #pragma unroll
        for (int tn = 0; tn < 8; tn++) {
            int col = blockIdx.x * 128 + warpN * 64 + tn * 8 + 2 * t;
            float bx = __ldg(&bias[col]);
            float by = __ldg(&bias[col + 1]);
            float v00 = acc[tm][tn][0] + bx, v01 = acc[tm][tn][1] + by;
            float v10 = acc[tm][tn][2] + bx, v11 = acc[tm][tn][3] + by;
            if constexpr (sizeof(OT) == 2) {
                __half2 h0 = __floats2half2_rn(v00, v01);
                __half2 h1 = __floats2half2_rn(v10, v11);
                *(uint32_t*)((__half*)C + (size_t)row * N + col)       = *(uint32_t*)&h0;
                *(uint32_t*)((__half*)C + (size_t)(row + 8) * N + col) = *(uint32_t*)&h1;
            } else {
                *(float2*)((float*)C + (size_t)row * N + col)       = make_float2(v00, v01);
                *(float2*)((float*)C + (size_t)(row + 8) * N + col) = make_float2(v10, v11);
            }
        }
    }
}

// ---------------------------------------------------------------------------
// fp16 MMA flash attention (unchanged — R8 passing version).
// ---------------------------------------------------------------------------
#define QS 72

__global__ __launch_bounds__(256) void attn_f16(
    const __half* __restrict__ qkv, __half* __restrict__ out)
{
    __shared__ alignas(16) __half Ks[2][64 * QS];  // also Q staging (flat 128 rows)
    __shared__ alignas(16) __half Vs[2][64 * QS];

    const int tid  = threadIdx.x;
    const int warp = tid >> 5;
    const int lane = tid & 31;
    const int g    = lane >> 2;
    const int t    = lane & 3;
    const int b    = blockIdx.y >> 4;
    const int h    = blockIdx.y & 15;
    const int q0   = blockIdx.x * 128;

    const __half* base = qkv + (size_t)b * T_ * C3 + h * HD;
    const float qscale = 0.125f * 1.4426950408889634f;  // 1/sqrt(64) * log2(e)

    __half* Kflat = &Ks[0][0];

    {
        #pragma unroll
        for (int i = 0; i < 4; i++) {
            int c = tid + i * 256;
            int r = c >> 3, co = (c & 7) * 8;
            uint32_t sq = smem_u32(&Kflat[r * QS + co]);
            asm volatile("cp.async.cg.shared.global [%0], [%1], 16;"
                         :: "r"(sq), "l"(base + (size_t)(q0 + r) * C3 + co));
        }
        asm volatile("cp.async.commit_group;");
        asm volatile("cp.async.wait_group 0;" ::: "memory");
    }
    __syncthreads();

    uint32_t qf[4][4];
    {
        int row = warp * 16 + (lane & 15);
        #pragma unroll
        for (int ks = 0; ks < 4; ks++) {
            uint32_t addr = smem_u32(&Kflat[row * QS + ks * 16 + (lane >> 4) * 8]);
            asm volatile("ldmatrix.sync.aligned.m8n8.x4.shared.b16 "
                         "{%0,%1,%2,%3}, [%4];"
                         : "=r"(qf[ks][0]), "=r"(qf[ks][1]),
                           "=r"(qf[ks][2]), "=r"(qf[ks][3])
                         : "r"(addr));
        }
    }
    __syncthreads();

    {
        #pragma unroll
        for (int i = 0; i < 2; i++) {
            int c = tid + i * 256;
            int r = c >> 3, co = (c & 7) * 8;
            uint32_t sk = smem_u32(&Ks[0][r * QS + co]);
            asm volatile("cp.async.cg.shared.global [%0], [%1], 16;"
                         :: "r"(sk), "l"(base + (size_t)r * C3 + N_EMBD + co));
            uint32_t sv = smem_u32(&Vs[0][r * QS + co]);
            asm volatile("cp.async.cg.shared.global [%0], [%1], 16;"
                         :: "r"(sv), "l"(base + (size_t)r * C3 + 2 * N_EMBD + co));
        }
        asm volatile("cp.async.commit_group;");
        asm volatile("cp.async.wait_group 0;" ::: "memory");
    }
    __syncthreads();

    float o[8][4];
    #pragma unroll
    for (int tn = 0; tn < 8; tn++)
        #pragma unroll
        for (int c = 0; c < 4; c++) o[tn][c] = 0.f;
    float m0 = -1e30f, m1 = -1e30f, l0 = 0.f, l1 = 0.f;

    const int NT = (q0 >> 6) + 2;
    for (int jt = 0; jt < NT; jt++) {
        const int s  = jt & 1;
        const int j0 = jt << 6;

        if (jt + 1 < NT) {
            const int ns = s ^ 1;
            const int nj = j0 + 64;
            #pragma unroll
            for (int i = 0; i < 2; i++) {
                int c = tid + i * 256;
                int r = c >> 3, co = (c & 7) * 8;
                uint32_t sk = smem_u32(&Ks[ns][r * QS + co]);
                asm volatile("cp.async.cg.shared.global [%0], [%1], 16;"
                             :: "r"(sk), "l"(base + (size_t)(nj + r) * C3 + N_EMBD + co));
                uint32_t sv = smem_u32(&Vs[ns][r * QS + co]);
                asm volatile("cp.async.cg.shared.global [%0], [%1], 16;"
                             :: "r"(sv), "l"(base + (size_t)(nj + r) * C3 + 2 * N_EMBD + co));
            }
            asm volatile("cp.async.commit_group;");
        }

        const bool active = (j0 <= q0 + warp * 16 + 15);
        if (active) {
            float acc[8][4];
            #pragma unroll
            for (int tn = 0; tn < 8; tn++)
                #pragma unroll
                for (int c = 0; c < 4; c++) acc[tn][c] = 0.f;

            #pragma unroll
            for (int ks = 0; ks < 4; ks++) {
                #pragma unroll
                for (int tn = 0; tn < 8; tn++) {
                    uint32_t b0 = *(const uint32_t*)&Ks[s][(tn * 8 + g) * QS + ks * 16 + 2 * t];
                    uint32_t b1 = *(const uint32_t*)&Ks[s][(tn * 8 + g) * QS + ks * 16 + 2 * t + 8];
                    asm volatile(
                        "mma.sync.aligned.m16n8k16.row.col.f32.f16.f16.f32 "
                        "{%0,%1,%2,%3}, {%4,%5,%6,%7}, {%8,%9}, {%0,%1,%2,%3};"
                        : "+f"(acc[tn][0]), "+f"(acc[tn][1]),
                          "+f"(acc[tn][2]), "+f"(acc[tn][3])
                        : "r"(qf[ks][0]), "r"(qf[ks][1]), "r"(qf[ks][2]), "r"(qf[ks][3]),
                          "r"(b0), "r"(b1));
                }
            }

            #pragma unroll
            for (int tn = 0; tn < 8; tn++) {
                acc[tn][0] *= qscale; acc[tn][1] *= qscale;
                acc[tn][2] *= qscale; acc[tn][3] *= qscale;
            }
            if (j0 + 63 > q0 + warp * 16) {
                int r0 = q0 + warp * 16 + g;
                #pragma unroll
                for (int tn = 0; tn < 8; tn++) {
                    int c0 = j0 + tn * 8 + 2 * t;
                    if (c0     > r0)     acc[tn][0] = -1e30f;
                    if (c0 + 1 > r0)     acc[tn][1] = -1e30f;
                    if (c0     > r0 + 8) acc[tn][2] = -1e30f;
                    if (c0 + 1 > r0 + 8) acc[tn][3] = -1e30f;
                }
            }

            float mx0 = -1e30f, mx1 = -1e30f;
            #pragma unroll
            for (int tn = 0; tn < 8; tn++) {
                mx0 = fmaxf(mx0, fmaxf(acc[tn][0], acc[tn][1]));
                mx1 = fmaxf(mx1, fmaxf(acc[tn][2], acc[tn][3]));
            }
            mx0 = fmaxf(mx0, __shfl_xor_sync(0xffffffffu, mx0, 1));
            mx0 = fmaxf(mx0, __shfl_xor_sync(0xffffffffu, mx0, 2));
            mx1 = fmaxf(mx1, __shfl_xor_sync(0xffffffffu, mx1, 1));
            mx1 = fmaxf(mx1, __shfl_xor_sync(0xffffffffu, mx1, 2));

            float mn0 = fmaxf(m0, mx0), mn1 = fmaxf(m1, mx1);
            float cr0 = ex2(m0 - mn0),  cr1 = ex2(m1 - mn1);
            l0 *= cr0; l1 *= cr1;
            m0 = mn0;  m1 = mn1;
            #pragma unroll
            for (int tn = 0; tn < 8; tn++) {
                o[tn][0] *= cr0; o[tn][1] *= cr0;
                o[tn][2] *= cr1; o[tn][3] *= cr1;
            }

            uint32_t ph01[8], ph23[8];
            #pragma unroll
            for (int tn = 0; tn < 8; tn++) {
                float p0 = ex2(acc[tn][0] - m0);
                float p1 = ex2(acc[tn][1] - m0);
                float p2 = ex2(acc[tn][2] - m1);
                float p3 = ex2(acc[tn][3] - m1);
                l0 += p0 + p1;
                l1 += p2 + p3;
                __half2 h01 = __floats2half2_rn(p0, p1);
                __half2 h23 = __floats2half2_rn(p2, p3);
                ph01[tn] = *(uint32_t*)&h01;
                ph23[tn] = *(uint32_t*)&h23;
            }

            #pragma unroll
            for (int kc = 0; kc < 4; kc++) {
                uint32_t a0 = ph01[2 * kc],     a1 = ph23[2 * kc];
                uint32_t a2 = ph01[2 * kc + 1], a3 = ph23[2 * kc + 1];
                #pragma unroll
                for (int tp = 0; tp < 4; tp++) {
                    uint32_t v0, v1, v2, v3;
                    uint32_t addr = smem_u32(
                        &Vs[s][(kc * 16 + ((lane >> 3) & 1) * 8 + (lane & 7)) * QS
                               + (tp * 2 + (lane >> 4)) * 8]);
                    asm volatile("ldmatrix.sync.aligned.m8n8.x4.trans.shared.b16 "
                                 "{%0,%1,%2,%3}, [%4];"
                                 : "=r"(v0), "=r"(v1), "=r"(v2), "=r"(v3)
                                 : "r"(addr));
                    asm volatile(
                        "mma.sync.aligned.m16n8k16.row.col.f32.f16.f16.f32 "
                        "{%0,%1,%2,%3}, {%4,%5,%6,%7}, {%8,%9}, {%0,%1,%2,%3};"
                        : "+f"(o[tp * 2][0]), "+f"(o[tp * 2][1]),
                          "+f"(o[tp * 2][2]), "+f"(o[tp * 2][3])
                        : "r"(a0), "r"(a1), "r"(a2), "r"(a3), "r"(v0), "r"(v1));
                    asm volatile(
                        "mma.sync.aligned.m16n8k16.row.col.f32.f16.f16.f32 "
                        "{%0,%1,%2,%3}, {%4,%5,%6,%7}, {%8,%9}, {%0,%1,%2,%3};"
                        : "+f"(o[tp * 2 + 1][0]), "+f"(o[tp * 2 + 1][1]),
                          "+f"(o[tp * 2 + 1][2]), "+f"(o[tp * 2 + 1][3])
                        : "r"(a0), "r"(a1), "r"(a2), "r"(a3), "r"(v2), "r"(v3));
                }
            }
        }

        if (jt + 1 < NT)
            asm volatile("cp.async.wait_group 0;" ::: "memory");
        __syncthreads();
    }

    l0 += __shfl_xor_sync(0xffffffffu, l0, 1);
    l0 += __shfl_xor_sync(0xffffffffu, l0, 2);
    l1 += __shfl_xor_sync(0xffffffffu, l1, 1);
    l1 += __shfl_xor_sync(0xffffffffu, l1, 2);
    float inv0 = 1.f / l0, inv1 = 1.f / l1;

    int qr = q0 + warp * 16 + g;
    __half* orow0 = out + (size_t)(b * T_ + qr) * N_EMBD + h * HD;
    __half* orow1 = orow0 + (size_t)8 * N_EMBD;
    #pragma unroll
    for (int tn = 0; tn < 8; tn++) {
        int col = tn * 8 + 2 * t;
        __half2 w0 = __floats2half2_rn(o[tn][0] * inv0, o[tn][1] * inv0);
        __half2 w1 = __floats2half2_rn(o[tn][2] * inv1, o[tn][3] * inv1);
        *(uint32_t*)(orow0 + col) = *(uint32_t*)&w0;
        *(uint32_t*)(orow1 + col) = *(uint32_t*)&w1;
    }
}

// ---------------------------------------------------------------------------
extern "C" void kernel_launch(void* const* d_in, const int* in_sizes, int n_in,
                              void* d_out, int out_size)
{
    const float* x      = (const float*)d_in[0];
    const float* qkv_w  = (const float*)d_in[1];
    const float* qkv_b  = (const float*)d_in[2];
    const float* proj_w = (const float*)d_in[3];
    const float* proj_b = (const float*)d_in[4];
    float* out = (float*)d_out;

    __half *qkv_h = nullptr, *att_h = nullptr, *x_h = nullptr,
           *qkvw_h = nullptr, *projw_h = nullptr;
    cudaGetSymbolAddress((void**)&qkv_h,   g_qkv_h);
    cudaGetSymbolAddress((void**)&att_h,   g_att_h);
    cudaGetSymbolAddress((void**)&x_h,     g_x_h);
    cudaGetSymbolAddress((void**)&qkvw_h,  g_qkvw_h);
    cudaGetSymbolAddress((void**)&projw_h, g_projw_h);

    cudaFuncSetAttribute(gemm_f16<__half>,
                         cudaFuncAttributeMaxDynamicSharedMemorySize, TC_DYN_BYTES);
    cudaFuncSetAttribute(gemm_f16<float>,
                         cudaFuncAttributeMaxDynamicSharedMemorySize, TC_DYN_BYTES);

    // 0) fp32 -> fp16 converts
    {
        int n4x = (M_TOK * N_EMBD) / 4;
        f2h_kernel<<<(n4x + 255) / 256, 256>>>(x, x_h, n4x);
        int n4q = (C3 * N_EMBD) / 4;
        f2h_kernel<<<(n4q + 255) / 256, 256>>>(qkv_w, qkvw_h, n4q);
        int n4p = (N_EMBD * N_EMBD) / 4;
        f2h_kernel<<<(n4p + 255) / 256, 256>>>(proj_w, projw_h, n4p);
    }

    // 1) QKV GEMM (fp16 in, fp16 out): [8192,1024] @ [3072,1024]^T
    dim3 g1(C3 / 128, M_TOK / 128);
    gemm_f16<__half><<<g1, 256, TC_DYN_BYTES>>>(x_h, qkvw_h, qkv_b, qkv_h,
                                                M_TOK, C3, N_EMBD);

    // 2) Causal attention (fp16 flash), fp16 out
    dim3 g2(T_ / 128, B_ * N_HEAD);
    attn_f16<<<g2, 256>>>(qkv_h, att_h);

    // 3) Output projection (fp32 out): [8192,1024] @ [1024,1024]^T
    dim3 g3(N_EMBD / 128, M_TOK / 128);
    gemm_f16<float><<<g3, 256, TC_DYN_BYTES>>>(att_h, projw_h, proj_b, out,
                                               M_TOK, N_EMBD, N_EMBD);
}

// round 17
// speedup vs baseline: 1.2650x; 1.2650x over previous
#include <cuda_runtime.h>
#include <cuda_fp16.h>
#include <math.h>
#include <stdint.h>

#define N_HEAD 16
#define N_EMBD 1024
#define HD     64
#define B_     4
#define T_     2048
#define M_TOK  (B_ * T_)
#define C3     (3 * N_EMBD)

// Scratch (device globals — no allocation allowed in kernel_launch)
__device__ __half g_qkv_h[(size_t)M_TOK * C3];        // [B*T, 3C] fp16
__device__ __half g_att_h[(size_t)M_TOK * N_EMBD];    // attention out, fp16
__device__ __half g_x_h[(size_t)M_TOK * N_EMBD];      // x in fp16
__device__ __half g_qkvw_h[(size_t)C3 * N_EMBD];      // qkv_w fp16
__device__ __half g_projw_h[(size_t)N_EMBD * N_EMBD]; // proj_w fp16

__device__ __forceinline__ float ex2(float x) {
    float r;
    asm("ex2.approx.ftz.f32 %0, %1;" : "=f"(r) : "f"(x));
    return r;
}
__device__ __forceinline__ uint32_t smem_u32(const void* p) {
    return (uint32_t)__cvta_generic_to_shared(p);
}

// ---------------------------------------------------------------------------
// fp32 -> fp16 convert (vectorized)
// ---------------------------------------------------------------------------
__global__ __launch_bounds__(256) void f2h_kernel(
    const float* __restrict__ in, __half* __restrict__ out, int n4)
{
    int i = blockIdx.x * 256 + threadIdx.x;
    if (i < n4) {
        float4 v = *(const float4*)(in + (size_t)i * 4);
        __half2 lo = __floats2half2_rn(v.x, v.y);
        __half2 hi = __floats2half2_rn(v.z, v.w);
        uint2 o = make_uint2(*(uint32_t*)&lo, *(uint32_t*)&hi);
        *(uint2*)(out + (size_t)i * 4) = o;
    }
}

// ---------------------------------------------------------------------------
// fp16 tensor-core GEMM (R8 structure): C[M,N] = A[M,K] @ W[N,K]^T + bias[N]
// 128x128 block tile, BK=32, 3-stage cp.async pipeline, static 48KB smem,
// XOR-swizzled (stride 32 halves, chunk c ^ ((r^(r>>2))&3)),
// ldmatrix.x4 A and B fragments. 8 warps (4M x 2N).
// __launch_bounds__(256,2): regs capped at 128 -> guaranteed 2 CTAs/SM.
// ONE __syncthreads per K-iteration (top sync covers buffer-reuse hazard).
// ---------------------------------------------------------------------------
template <typename OT>
__global__ __launch_bounds__(256, 2) void gemm_f16(
    const __half* __restrict__ A, const __half* __restrict__ W,
    const float* __restrict__ bias, OT* __restrict__ C,
    int M, int N, int K)
{
    __shared__ alignas(16) __half As[3][128 * 32];
    __shared__ alignas(16) __half Bs[3][128 * 32];

    const int tid   = threadIdx.x;
    const int warp  = tid >> 5;
    const int lane  = tid & 31;
    const int warpM = warp & 3;
    const int warpN = warp >> 2;
    const int g     = lane >> 2;
    const int t     = lane & 3;

    const __half* Ab = A + (size_t)blockIdx.y * 128 * K;
    const __half* Wb = W + (size_t)blockIdx.x * 128 * K;

    const int lr = tid >> 2;       // load row (0..63), +64 on second pass
    const int lc = tid & 3;        // 16B chunk within 64B row

    const int KT = K >> 5;         // #32-wide K tiles

    auto issue = [&](int kt, int st) {
        const int k0 = kt << 5;
        #pragma unroll
        for (int i = 0; i < 2; i++) {
            int r  = lr + i * 64;
            int pc = (lc ^ (r ^ (r >> 2))) & 3;
            uint32_t sa = smem_u32(&As[st][r * 32 + pc * 8]);
            asm volatile("cp.async.cg.shared.global [%0], [%1], 16;"
                         :: "r"(sa), "l"(Ab + (size_t)r * K + k0 + lc * 8));
            uint32_t sb = smem_u32(&Bs[st][r * 32 + pc * 8]);
            asm volatile("cp.async.cg.shared.global [%0], [%1], 16;"
                         :: "r"(sb), "l"(Wb + (size_t)r * K + k0 + lc * 8));
        }
        asm volatile("cp.async.commit_group;");
    };

    // Prologue: tiles 0 and 1 in flight
    issue(0, 0);
    issue(1, 1);

    float acc[2][8][4];
    #pragma unroll
    for (int i = 0; i < 2; i++)
        #pragma unroll
        for (int j = 0; j < 8; j++)
            #pragma unroll
            for (int c = 0; c < 4; c++) acc[i][j][c] = 0.f;

    int s = 0;
    for (int kt = 0; kt < KT; kt++) {
        if (kt + 1 < KT) asm volatile("cp.async.wait_group 1;" ::: "memory");
        else             asm volatile("cp.async.wait_group 0;" ::: "memory");
        __syncthreads();
        // After this barrier every warp has finished reading stage (kt-1)%3,
        // which is exactly the buffer issue(kt+2) overwrites -> no bottom sync.

        if (kt + 2 < KT) {
            int ns = s + 2; if (ns >= 3) ns -= 3;
            issue(kt + 2, ns);
        }

        #pragma unroll
        for (int ks = 0; ks < 2; ks++) {
            // A fragments: 2 x ldmatrix.x4 (m16k16 tiles)
            uint32_t af[2][4];
            #pragma unroll
            for (int tm = 0; tm < 2; tm++) {
                int row = warpM * 32 + tm * 16 + (lane & 15);
                int c   = ks * 2 + (lane >> 4);
                int pc  = (c ^ (row ^ (row >> 2))) & 3;
                uint32_t addr = smem_u32(&As[s][row * 32 + pc * 8]);
                asm volatile("ldmatrix.sync.aligned.m8n8.x4.shared.b16 "
                             "{%0,%1,%2,%3}, [%4];"
                             : "=r"(af[tm][0]), "=r"(af[tm][1]),
                               "=r"(af[tm][2]), "=r"(af[tm][3])
                             : "r"(addr));
            }
            // B fragments: 4 x ldmatrix.x4, each covers two n8 tiles
            uint32_t bf[8][2];
            #pragma unroll
            for (int tnp = 0; tnp < 4; tnp++) {
                int n  = warpN * 64 + tnp * 16 + ((lane >> 4) << 3) + (lane & 7);
                int c  = ks * 2 + ((lane >> 3) & 1);
                int pc = (c ^ (n ^ (n >> 2))) & 3;
                uint32_t addr = smem_u32(&Bs[s][n * 32 + pc * 8]);
                asm volatile("ldmatrix.sync.aligned.m8n8.x4.shared.b16 "
                             "{%0,%1,%2,%3}, [%4];"
                             : "=r"(bf[2 * tnp][0]),     "=r"(bf[2 * tnp][1]),
                               "=r"(bf[2 * tnp + 1][0]), "=r"(bf[2 * tnp + 1][1])
                             : "r"(addr));
            }
            #pragma unroll
            for (int tn = 0; tn < 8; tn++)
                #pragma unroll
                for (int tm = 0; tm < 2; tm++) {
                    asm volatile(
                        "mma.sync.aligned.m16n8k16.row.col.f32.f16.f16.f32 "
                        "{%0,%1,%2,%3}, {%4,%5,%6,%7}, {%8,%9}, {%0,%1,%2,%3};"
                        : "+f"(acc[tm][tn][0]), "+f"(acc[tm][tn][1]),
                          "+f"(acc[tm][tn][2]), "+f"(acc[tm][tn][3])
                        : "r"(af[tm][0]), "r"(af[tm][1]),
                          "r"(af[tm][2]), "r"(af[tm][3]),
                          "r"(bf[tn][0]), "r"(bf[tn][1]));
                }
        }
        if (++s == 3) s = 0;
    }

    #pragma unroll
    for (int tm = 0; tm < 2; tm++) {
        int row = blockIdx.y * 128 + warpM * 32 + tm * 16 + g;
        #pragma unroll
        for (int tn = 0; tn < 8; tn++) {
            int col = blockIdx.x * 128 + warpN * 64 + tn * 8 + 2 * t;
            float bx = __ldg(&bias[col]);
            float by = __ldg(&bias[col + 1]);
            float v00 = acc[tm][tn][0] + bx, v01 = acc[tm][tn][1] + by;
            float v10 = acc[tm][tn][2] + bx, v11 = acc[tm][tn][3] + by;
            if constexpr (sizeof(OT) == 2) {
                __half2 h0 = __floats2half2_rn(v00, v01);
                __half2 h1 = __floats2half2_rn(v10, v11);
                *(uint32_t*)((__half*)C + (size_t)row * N + col)       = *(uint32_t*)&h0;
                *(uint32_t*)((__half*)C + (size_t)(row + 8) * N + col) = *(uint32_t*)&h1;
            } else {
                *(float2*)((float*)C + (size_t)row * N + col)       = make_float2(v00, v01);
                *(float2*)((float*)C + (size_t)(row + 8) * N + col) = make_float2(v10, v11);
            }
        }
    }
}

// ---------------------------------------------------------------------------
// fp16 MMA flash attention (unchanged — R8 passing version).
// ---------------------------------------------------------------------------
#define QS 72

__global__ __launch_bounds__(256) void attn_f16(
    const __half* __restrict__ qkv, __half* __restrict__ out)
{
    __shared__ alignas(16) __half Ks[2][64 * QS];  // also Q staging (flat 128 rows)
    __shared__ alignas(16) __half Vs[2][64 * QS];

    const int tid  = threadIdx.x;
    const int warp = tid >> 5;
    const int lane = tid & 31;
    const int g    = lane >> 2;
    const int t    = lane & 3;
    const int b    = blockIdx.y >> 4;
    const int h    = blockIdx.y & 15;
    const int q0   = blockIdx.x * 128;

    const __half* base = qkv + (size_t)b * T_ * C3 + h * HD;
    const float qscale = 0.125f * 1.4426950408889634f;  // 1/sqrt(64) * log2(e)

    __half* Kflat = &Ks[0][0];

    {
        #pragma unroll
        for (int i = 0; i < 4; i++) {
            int c = tid + i * 256;
            int r = c >> 3, co = (c & 7) * 8;
            uint32_t sq = smem_u32(&Kflat[r * QS + co]);
            asm volatile("cp.async.cg.shared.global [%0], [%1], 16;"
                         :: "r"(sq), "l"(base + (size_t)(q0 + r) * C3 + co));
        }
        asm volatile("cp.async.commit_group;");
        asm volatile("cp.async.wait_group 0;" ::: "memory");
    }
    __syncthreads();

    uint32_t qf[4][4];
    {
        int row = warp * 16 + (lane & 15);
        #pragma unroll
        for (int ks = 0; ks < 4; ks++) {
            uint32_t addr = smem_u32(&Kflat[row * QS + ks * 16 + (lane >> 4) * 8]);
            asm volatile("ldmatrix.sync.aligned.m8n8.x4.shared.b16 "
                         "{%0,%1,%2,%3}, [%4];"
                         : "=r"(qf[ks][0]), "=r"(qf[ks][1]),
                           "=r"(qf[ks][2]), "=r"(qf[ks][3])
                         : "r"(addr));
        }
    }
    __syncthreads();

    {
        #pragma unroll
        for (int i = 0; i < 2; i++) {
            int c = tid + i * 256;
            int r = c >> 3, co = (c & 7) * 8;
            uint32_t sk = smem_u32(&Ks[0][r * QS + co]);
            asm volatile("cp.async.cg.shared.global [%0], [%1], 16;"
                         :: "r"(sk), "l"(base + (size_t)r * C3 + N_EMBD + co));
            uint32_t sv = smem_u32(&Vs[0][r * QS + co]);
            asm volatile("cp.async.cg.shared.global [%0], [%1], 16;"
                         :: "r"(sv), "l"(base + (size_t)r * C3 + 2 * N_EMBD + co));
        }
        asm volatile("cp.async.commit_group;");
        asm volatile("cp.async.wait_group 0;" ::: "memory");
    }
    __syncthreads();

    float o[8][4];
    #pragma unroll
    for (int tn = 0; tn < 8; tn++)
        #pragma unroll
        for (int c = 0; c < 4; c++) o[tn][c] = 0.f;
    float m0 = -1e30f, m1 = -1e30f, l0 = 0.f, l1 = 0.f;

    const int NT = (q0 >> 6) + 2;
    for (int jt = 0; jt < NT; jt++) {
        const int s  = jt & 1;
        const int j0 = jt << 6;

        if (jt + 1 < NT) {
            const int ns = s ^ 1;
            const int nj = j0 + 64;
            #pragma unroll
            for (int i = 0; i < 2; i++) {
                int c = tid + i * 256;
                int r = c >> 3, co = (c & 7) * 8;
                uint32_t sk = smem_u32(&Ks[ns][r * QS + co]);
                asm volatile("cp.async.cg.shared.global [%0], [%1], 16;"
                             :: "r"(sk), "l"(base + (size_t)(nj + r) * C3 + N_EMBD + co));
                uint32_t sv = smem_u32(&Vs[ns][r * QS + co]);
                asm volatile("cp.async.cg.shared.global [%0], [%1], 16;"
                             :: "r"(sv), "l"(base + (size_t)(nj + r) * C3 + 2 * N_EMBD + co));
            }
            asm volatile("cp.async.commit_group;");
        }

        const bool active = (j0 <= q0 + warp * 16 + 15);
        if (active) {
            float acc[8][4];
            #pragma unroll
            for (int tn = 0; tn < 8; tn++)
                #pragma unroll
                for (int c = 0; c < 4; c++) acc[tn][c] = 0.f;

            #pragma unroll
            for (int ks = 0; ks < 4; ks++) {
                #pragma unroll
                for (int tn = 0; tn < 8; tn++) {
                    uint32_t b0 = *(const uint32_t*)&Ks[s][(tn * 8 + g) * QS + ks * 16 + 2 * t];
                    uint32_t b1 = *(const uint32_t*)&Ks[s][(tn * 8 + g) * QS + ks * 16 + 2 * t + 8];
                    asm volatile(
                        "mma.sync.aligned.m16n8k16.row.col.f32.f16.f16.f32 "
                        "{%0,%1,%2,%3}, {%4,%5,%6,%7}, {%8,%9}, {%0,%1,%2,%3};"
                        : "+f"(acc[tn][0]), "+f"(acc[tn][1]),
                          "+f"(acc[tn][2]), "+f"(acc[tn][3])
                        : "r"(qf[ks][0]), "r"(qf[ks][1]), "r"(qf[ks][2]), "r"(qf[ks][3]),
                          "r"(b0), "r"(b1));
                }
            }

            #pragma unroll
            for (int tn = 0; tn < 8; tn++) {
                acc[tn][0] *= qscale; acc[tn][1] *= qscale;
                acc[tn][2] *= qscale; acc[tn][3] *= qscale;
            }
            if (j0 + 63 > q0 + warp * 16) {
                int r0 = q0 + warp * 16 + g;
                #pragma unroll
                for (int tn = 0; tn < 8; tn++) {
                    int c0 = j0 + tn * 8 + 2 * t;
                    if (c0     > r0)     acc[tn][0] = -1e30f;
                    if (c0 + 1 > r0)     acc[tn][1] = -1e30f;
                    if (c0     > r0 + 8) acc[tn][2] = -1e30f;
                    if (c0 + 1 > r0 + 8) acc[tn][3] = -1e30f;
                }
            }

            float mx0 = -1e30f, mx1 = -1e30f;
            #pragma unroll
            for (int tn = 0; tn < 8; tn++) {
                mx0 = fmaxf(mx0, fmaxf(acc[tn][0], acc[tn][1]));
                mx1 = fmaxf(mx1, fmaxf(acc[tn][2], acc[tn][3]));
            }
            mx0 = fmaxf(mx0, __shfl_xor_sync(0xffffffffu, mx0, 1));
            mx0 = fmaxf(mx0, __shfl_xor_sync(0xffffffffu, mx0, 2));
            mx1 = fmaxf(mx1, __shfl_xor_sync(0xffffffffu, mx1, 1));
            mx1 = fmaxf(mx1, __shfl_xor_sync(0xffffffffu, mx1, 2));

            float mn0 = fmaxf(m0, mx0), mn1 = fmaxf(m1, mx1);
            float cr0 = ex2(m0 - mn0),  cr1 = ex2(m1 - mn1);
            l0 *= cr0; l1 *= cr1;
            m0 = mn0;  m1 = mn1;
            #pragma unroll
            for (int tn = 0; tn < 8; tn++) {
                o[tn][0] *= cr0; o[tn][1] *= cr0;
                o[tn][2] *= cr1; o[tn][3] *= cr1;
            }

            uint32_t ph01[8], ph23[8];
            #pragma unroll
            for (int tn = 0; tn < 8; tn++) {
                float p0 = ex2(acc[tn][0] - m0);
                float p1 = ex2(acc[tn][1] - m0);
                float p2 = ex2(acc[tn][2] - m1);
                float p3 = ex2(acc[tn][3] - m1);
                l0 += p0 + p1;
                l1 += p2 + p3;
                __half2 h01 = __floats2half2_rn(p0, p1);
                __half2 h23 = __floats2half2_rn(p2, p3);
                ph01[tn] = *(uint32_t*)&h01;
                ph23[tn] = *(uint32_t*)&h23;
            }

            #pragma unroll
            for (int kc = 0; kc < 4; kc++) {
                uint32_t a0 = ph01[2 * kc],     a1 = ph23[2 * kc];
                uint32_t a2 = ph01[2 * kc + 1], a3 = ph23[2 * kc + 1];
                #pragma unroll
                for (int tp = 0; tp < 4; tp++) {
                    uint32_t v0, v1, v2, v3;
                    uint32_t addr = smem_u32(
                        &Vs[s][(kc * 16 + ((lane >> 3) & 1) * 8 + (lane & 7)) * QS
                               + (tp * 2 + (lane >> 4)) * 8]);
                    asm volatile("ldmatrix.sync.aligned.m8n8.x4.trans.shared.b16 "
                                 "{%0,%1,%2,%3}, [%4];"
                                 : "=r"(v0), "=r"(v1), "=r"(v2), "=r"(v3)
                                 : "r"(addr));
                    asm volatile(
                        "mma.sync.aligned.m16n8k16.row.col.f32.f16.f16.f32 "
                        "{%0,%1,%2,%3}, {%4,%5,%6,%7}, {%8,%9}, {%0,%1,%2,%3};"
                        : "+f"(o[tp * 2][0]), "+f"(o[tp * 2][1]),
                          "+f"(o[tp * 2][2]), "+f"(o[tp * 2][3])
                        : "r"(a0), "r"(a1), "r"(a2), "r"(a3), "r"(v0), "r"(v1));
                    asm volatile(
                        "mma.sync.aligned.m16n8k16.row.col.f32.f16.f16.f32 "
                        "{%0,%1,%2,%3}, {%4,%5,%6,%7}, {%8,%9}, {%0,%1,%2,%3};"
                        : "+f"(o[tp * 2 + 1][0]), "+f"(o[tp * 2 + 1][1]),
                          "+f"(o[tp * 2 + 1][2]), "+f"(o[tp * 2 + 1][3])
                        : "r"(a0), "r"(a1), "r"(a2), "r"(a3), "r"(v2), "r"(v3));
                }
            }
        }

        if (jt + 1 < NT)
            asm volatile("cp.async.wait_group 0;" ::: "memory");
        __syncthreads();
    }

    l0 += __shfl_xor_sync(0xffffffffu, l0, 1);
    l0 += __shfl_xor_sync(0xffffffffu, l0, 2);
    l1 += __shfl_xor_sync(0xffffffffu, l1, 1);
    l1 += __shfl_xor_sync(0xffffffffu, l1, 2);
    float inv0 = 1.f / l0, inv1 = 1.f / l1;

    int qr = q0 + warp * 16 + g;
    __half* orow0 = out + (size_t)(b * T_ + qr) * N_EMBD + h * HD;
    __half* orow1 = orow0 + (size_t)8 * N_EMBD;
    #pragma unroll
    for (int tn = 0; tn < 8; tn++) {
        int col = tn * 8 + 2 * t;
        __half2 w0 = __floats2half2_rn(o[tn][0] * inv0, o[tn][1] * inv0);
        __half2 w1 = __floats2half2_rn(o[tn][2] * inv1, o[tn][3] * inv1);
        *(uint32_t*)(orow0 + col) = *(uint32_t*)&w0;
        *(uint32_t*)(orow1 + col) = *(uint32_t*)&w1;
    }
}

// ---------------------------------------------------------------------------
extern "C" void kernel_launch(void* const* d_in, const int* in_sizes, int n_in,
                              void* d_out, int out_size)
{
    const float* x      = (const float*)d_in[0];
    const float* qkv_w  = (const float*)d_in[1];
    const float* qkv_b  = (const float*)d_in[2];
    const float* proj_w = (const float*)d_in[3];
    const float* proj_b = (const float*)d_in[4];
    float* out = (float*)d_out;

    __half *qkv_h = nullptr, *att_h = nullptr, *x_h = nullptr,
           *qkvw_h = nullptr, *projw_h = nullptr;
    cudaGetSymbolAddress((void**)&qkv_h,   g_qkv_h);
    cudaGetSymbolAddress((void**)&att_h,   g_att_h);
    cudaGetSymbolAddress((void**)&x_h,     g_x_h);
    cudaGetSymbolAddress((void**)&qkvw_h,  g_qkvw_h);
    cudaGetSymbolAddress((void**)&projw_h, g_projw_h);

    // 0) fp32 -> fp16 converts
    {
        int n4x = (M_TOK * N_EMBD) / 4;
        f2h_kernel<<<(n4x + 255) / 256, 256>>>(x, x_h, n4x);
        int n4q = (C3 * N_EMBD) / 4;
        f2h_kernel<<<(n4q + 255) / 256, 256>>>(qkv_w, qkvw_h, n4q);
        int n4p = (N_EMBD * N_EMBD) / 4;
        f2h_kernel<<<(n4p + 255) / 256, 256>>>(proj_w, projw_h, n4p);
    }

    // 1) QKV GEMM (fp16 in, fp16 out): [8192,1024] @ [3072,1024]^T
    dim3 g1(C3 / 128, M_TOK / 128);
    gemm_f16<__half><<<g1, 256>>>(x_h, qkvw_h, qkv_b, qkv_h, M_TOK, C3, N_EMBD);

    // 2) Causal attention (fp16 flash), fp16 out
    dim3 g2(T_ / 128, B_ * N_HEAD);
    attn_f16<<<g2, 256>>>(qkv_h, att_h);

    // 3) Output projection (fp32 out): [8192,1024] @ [1024,1024]^T
    dim3 g3(N_EMBD / 128, M_TOK / 128);
    gemm_f16<float><<<g3, 256>>>(att_h, projw_h, proj_b, out, M_TOK, N_EMBD, N_EMBD);
}